// round 1
// baseline (speedup 1.0000x reference)
#include <cuda_runtime.h>
#include <cuda_bf16.h>
#include <stdint.h>

// Problem dims (fixed)
#define BB 4096   // batch
#define DD 2048   // input dim
#define LL 16384  // latent dim
#define KK 64     // topk

// ---------------- scratch (static device globals: no runtime allocation) ----
__device__ float g_Wt[(size_t)LL * DD];   // W transposed: [L, D], 128 MB
__device__ int   g_topk_idx[BB * KK];
__device__ float g_topk_val[BB * KK];

// ---------------- W transpose: Wt[l, d] = W[d, l] ---------------------------
__global__ void transpose_kernel(const float* __restrict__ W) {
    __shared__ float tile[32][33];
    int l0 = blockIdx.x * 32;
    int d0 = blockIdx.y * 32;
    int tx = threadIdx.x;      // 0..31
    int ty = threadIdx.y;      // 0..7
    // read: rows of W (coalesced along l)
    #pragma unroll
    for (int r = ty; r < 32; r += 8) {
        tile[r][tx] = W[(size_t)(d0 + r) * LL + (l0 + tx)];
    }
    __syncthreads();
    // write: rows of Wt (coalesced along d)
    #pragma unroll
    for (int r = ty; r < 32; r += 8) {
        g_Wt[(size_t)(l0 + r) * DD + (d0 + tx)] = tile[tx][r];
    }
}

// ---------------- encode GEMM: Z = X @ W + b_enc -----------------------------
// X: [B, D] row-major, W: [D, L] row-major, Z: [B, L]
// 128x128 tile, BK=8, 256 threads, 8x8 micro-tile per thread.
#define BM 128
#define BN 128
#define BKk 8

__global__ __launch_bounds__(256) void encode_gemm_kernel(
    const float* __restrict__ X, const float* __restrict__ W,
    const float* __restrict__ benc, float* __restrict__ Z)
{
    __shared__ float As[BKk][BM];
    __shared__ float Bs[BKk][BN];

    const int tid = threadIdx.x;
    const int tx = tid & 15;     // 0..15 -> col group
    const int ty = tid >> 4;     // 0..15 -> row group
    const int row0 = blockIdx.y * BM;
    const int col0 = blockIdx.x * BN;

    // A load mapping: 1024 floats = 256 float4s. thread t -> row t/2, 4-col (t%2)*4
    const int aRow = tid >> 1;
    const int aCol = (tid & 1) * 4;
    // B load mapping: 8 rows x 128 cols. thread t -> row t/32, col (t%32)*4
    const int bRow = tid >> 5;
    const int bCol = (tid & 31) * 4;

    float acc[8][8];
    #pragma unroll
    for (int i = 0; i < 8; i++)
        #pragma unroll
        for (int j = 0; j < 8; j++) acc[i][j] = 0.0f;

    for (int k0 = 0; k0 < DD; k0 += BKk) {
        float4 av = *(const float4*)(X + (size_t)(row0 + aRow) * DD + k0 + aCol);
        float4 bv = *(const float4*)(W + (size_t)(k0 + bRow) * LL + col0 + bCol);
        As[aCol + 0][aRow] = av.x;
        As[aCol + 1][aRow] = av.y;
        As[aCol + 2][aRow] = av.z;
        As[aCol + 3][aRow] = av.w;
        *(float4*)&Bs[bRow][bCol] = bv;
        __syncthreads();

        #pragma unroll
        for (int kk = 0; kk < BKk; kk++) {
            float a[8], b[8];
            float4 a0 = *(const float4*)&As[kk][ty * 8];
            float4 a1 = *(const float4*)&As[kk][ty * 8 + 4];
            float4 b0 = *(const float4*)&Bs[kk][tx * 8];
            float4 b1 = *(const float4*)&Bs[kk][tx * 8 + 4];
            a[0]=a0.x; a[1]=a0.y; a[2]=a0.z; a[3]=a0.w;
            a[4]=a1.x; a[5]=a1.y; a[6]=a1.z; a[7]=a1.w;
            b[0]=b0.x; b[1]=b0.y; b[2]=b0.z; b[3]=b0.w;
            b[4]=b1.x; b[5]=b1.y; b[6]=b1.z; b[7]=b1.w;
            #pragma unroll
            for (int i = 0; i < 8; i++)
                #pragma unroll
                for (int j = 0; j < 8; j++)
                    acc[i][j] = fmaf(a[i], b[j], acc[i][j]);
        }
        __syncthreads();
    }

    // epilogue: add bias, store
    float bias[8];
    {
        float4 c0 = *(const float4*)(benc + col0 + tx * 8);
        float4 c1 = *(const float4*)(benc + col0 + tx * 8 + 4);
        bias[0]=c0.x; bias[1]=c0.y; bias[2]=c0.z; bias[3]=c0.w;
        bias[4]=c1.x; bias[5]=c1.y; bias[6]=c1.z; bias[7]=c1.w;
    }
    #pragma unroll
    for (int i = 0; i < 8; i++) {
        int r = row0 + ty * 8 + i;
        float4 o0, o1;
        o0.x = acc[i][0] + bias[0];
        o0.y = acc[i][1] + bias[1];
        o0.z = acc[i][2] + bias[2];
        o0.w = acc[i][3] + bias[3];
        o1.x = acc[i][4] + bias[4];
        o1.y = acc[i][5] + bias[5];
        o1.z = acc[i][6] + bias[6];
        o1.w = acc[i][7] + bias[7];
        *(float4*)(Z + (size_t)r * LL + col0 + tx * 8)     = o0;
        *(float4*)(Z + (size_t)r * LL + col0 + tx * 8 + 4) = o1;
    }
}

// ---------------- per-row top-K select on |z| (radix select) ----------------
// One block per row. Keys = float bits of |z| (monotonic for non-negative).
// Dynamic smem: keys[L] (uint) + vals[L] (float) = 128 KB.
__global__ __launch_bounds__(256) void topk_kernel(float* __restrict__ Z)
{
    extern __shared__ unsigned char s_raw[];
    unsigned* s_keys = (unsigned*)s_raw;
    float*    s_vals = (float*)(s_raw + (size_t)LL * 4);

    __shared__ unsigned s_hist[256];
    __shared__ unsigned s_prefix;
    __shared__ int s_rem, s_eq, s_cutoff, s_pos;

    const int row = blockIdx.x;
    const int tid = threadIdx.x;
    const int NPT = LL / 256;  // 64 elements per thread
    float* zrow = Z + (size_t)row * LL;

    // load row
    #pragma unroll 4
    for (int e = 0; e < NPT; e++) {
        int i = e * 256 + tid;
        float v = zrow[i];
        s_vals[i] = v;
        s_keys[i] = __float_as_uint(fabsf(v));
    }
    if (tid == 0) { s_prefix = 0u; s_rem = KK; s_eq = 0; s_pos = 0; }
    __syncthreads();

    // 4-pass MSB radix select for the KK-th largest key
    #pragma unroll
    for (int shift = 24; shift >= 0; shift -= 8) {
        s_hist[tid & 255] = 0;   // blockDim == 256
        __syncthreads();
        unsigned pfx = s_prefix;
        unsigned hm = (shift == 24) ? 0u : (0xFFFFFFFFu << (shift + 8));
        for (int e = 0; e < NPT; e++) {
            unsigned kk = s_keys[e * 256 + tid];
            if (((kk ^ pfx) & hm) == 0)
                atomicAdd(&s_hist[(kk >> shift) & 255u], 1u);
        }
        __syncthreads();
        if (tid == 0) {
            int r = s_rem;
            unsigned p = s_prefix;
            for (int b = 255; b >= 0; b--) {
                int c = (int)s_hist[b];
                if (c >= r) { s_prefix = p | ((unsigned)b << shift); break; }
                r -= c;
            }
            s_rem = r;  // rank needed within the chosen bin (-> within equals at the end)
        }
        __syncthreads();
    }

    const unsigned T = s_prefix;       // key value of the KK-th largest |z|
    const int need = s_rem;            // how many elements equal to T to include

    // count equals
    {
        int cnt = 0;
        for (int e = 0; e < NPT; e++)
            if (s_keys[e * 256 + tid] == T) cnt++;
        if (cnt) atomicAdd(&s_eq, cnt);
    }
    __syncthreads();

    // tie-break: lowest indices first (matches jax.lax.top_k)
    if (tid == 0) {
        if (need >= s_eq) {
            s_cutoff = 0x7FFFFFFF;     // select all equals
        } else {
            int c = 0, cut = 0x7FFFFFFF;
            for (int i = 0; i < LL; i++) {
                if (s_keys[i] == T) {
                    c++;
                    if (c == need) { cut = i; break; }
                }
            }
            s_cutoff = cut;
        }
    }
    __syncthreads();
    const int cutoff = s_cutoff;

    // write z_sparse in place + compact (idx, val) list
    for (int e = 0; e < NPT; e++) {
        int i = e * 256 + tid;
        unsigned kk = s_keys[i];
        float v = s_vals[i];
        bool sel = (kk > T) || (kk == T && i <= cutoff);
        zrow[i] = sel ? v : 0.0f;
        if (sel) {
            int p = atomicAdd(&s_pos, 1);
            g_topk_idx[row * KK + p] = i;
            g_topk_val[row * KK + p] = v;
        }
    }
}

// ---------------- decode: recon[b,:] = sum_j val_j * Wt[idx_j,:] + b_dec ----
__global__ __launch_bounds__(256) void decode_kernel(
    const float* __restrict__ bdec, float* __restrict__ R)
{
    __shared__ int   sidx[KK];
    __shared__ float sval[KK];
    const int row = blockIdx.x;
    const int tid = threadIdx.x;
    if (tid < KK) {
        sidx[tid] = g_topk_idx[row * KK + tid];
        sval[tid] = g_topk_val[row * KK + tid];
    }
    __syncthreads();

    const int d0 = tid * 8;  // 256 threads * 8 = 2048
    float acc[8];
    {
        float4 b0 = *(const float4*)(bdec + d0);
        float4 b1 = *(const float4*)(bdec + d0 + 4);
        acc[0]=b0.x; acc[1]=b0.y; acc[2]=b0.z; acc[3]=b0.w;
        acc[4]=b1.x; acc[5]=b1.y; acc[6]=b1.z; acc[7]=b1.w;
    }
    #pragma unroll 4
    for (int j = 0; j < KK; j++) {
        const float v = sval[j];
        const float* wp = g_Wt + (size_t)sidx[j] * DD + d0;
        float4 w0 = *(const float4*)(wp);
        float4 w1 = *(const float4*)(wp + 4);
        acc[0] = fmaf(v, w0.x, acc[0]);
        acc[1] = fmaf(v, w0.y, acc[1]);
        acc[2] = fmaf(v, w0.z, acc[2]);
        acc[3] = fmaf(v, w0.w, acc[3]);
        acc[4] = fmaf(v, w1.x, acc[4]);
        acc[5] = fmaf(v, w1.y, acc[5]);
        acc[6] = fmaf(v, w1.z, acc[6]);
        acc[7] = fmaf(v, w1.w, acc[7]);
    }
    float4 o0, o1;
    o0.x=acc[0]; o0.y=acc[1]; o0.z=acc[2]; o0.w=acc[3];
    o1.x=acc[4]; o1.y=acc[5]; o1.z=acc[6]; o1.w=acc[7];
    *(float4*)(R + (size_t)row * DD + d0)     = o0;
    *(float4*)(R + (size_t)row * DD + d0 + 4) = o1;
}

// ---------------- launch ------------------------------------------------------
extern "C" void kernel_launch(void* const* d_in, const int* in_sizes, int n_in,
                              void* d_out, int out_size)
{
    const float* X    = (const float*)d_in[0];  // [B, D]
    const float* W    = (const float*)d_in[1];  // [D, L]
    const float* benc = (const float*)d_in[2];  // [L]
    const float* bdec = (const float*)d_in[3];  // [D]
    // d_in[4] = k (always 64 here)

    float* recon = (float*)d_out;                         // [B, D]
    float* Z     = (float*)d_out + (size_t)BB * DD;       // [B, L] -> z_sparse in place

    // opt-in to 128 KB dynamic smem for the topk kernel
    static int smem_set = 0;
    if (!smem_set) {
        cudaFuncSetAttribute(topk_kernel,
                             cudaFuncAttributeMaxDynamicSharedMemorySize,
                             LL * 8 + 1024);
        smem_set = 1;
    }

    // 1) transpose W -> Wt (for coalesced decode gather)
    {
        dim3 grid(LL / 32, DD / 32);
        dim3 block(32, 8);
        transpose_kernel<<<grid, block>>>(W);
    }
    // 2) encode GEMM: Z = X @ W + b_enc
    {
        dim3 grid(LL / BN, BB / BM);
        encode_gemm_kernel<<<grid, 256>>>(X, W, benc, Z);
    }
    // 3) per-row top-64 on |z|: Z -> z_sparse in place, compact lists
    {
        topk_kernel<<<BB, 256, LL * 8 + 1024>>>(Z);
    }
    // 4) decode: recon = z_sparse @ W^T + b_dec (sparse gather form)
    {
        decode_kernel<<<BB, 256>>>(bdec, recon);
    }
}

// round 3
// speedup vs baseline: 4.8620x; 4.8620x over previous
#include <cuda_runtime.h>
#include <cuda_fp16.h>
#include <cuda_bf16.h>
#include <stdint.h>

// Problem dims (fixed)
#define BB 4096   // batch
#define DD 2048   // input dim
#define LL 16384  // latent dim
#define KK 64     // topk
#define CAND_MAX 512

// ---------------- scratch (static device globals) ---------------------------
__device__ float         g_Wt[(size_t)LL * DD];    // W^T fp32 [L, D] (recompute/decode)
__device__ __nv_bfloat16 g_WB[(size_t)DD * LL];    // W bf16  [D, L] (GEMM B, k-major)
__device__ __nv_bfloat16 g_XB[(size_t)BB * DD];    // X bf16  [B, D]
__device__ __half        g_Zh[(size_t)BB * LL];    // |z_approx| half [B, L]
__device__ int           g_cand[(size_t)BB * CAND_MAX];
__device__ int           g_cand_cnt[BB];
__device__ int           g_topk_idx[BB * KK];
__device__ float         g_topk_val[BB * KK];

// ---------------- mma.sync helpers (plain sm_80+ PTX, no arch-suffix) -------
__device__ __forceinline__ void cp16(uint32_t dst, const void* src) {
    asm volatile("cp.async.cg.shared.global [%0], [%1], 16;\n" :: "r"(dst), "l"(src));
}

__device__ __forceinline__ void ldsm_x4(uint32_t* r, uint32_t addr) {
    asm volatile("ldmatrix.sync.aligned.m8n8.x4.shared.b16 {%0,%1,%2,%3}, [%4];"
                 : "=r"(r[0]), "=r"(r[1]), "=r"(r[2]), "=r"(r[3]) : "r"(addr));
}

__device__ __forceinline__ void ldsm_x4_t(uint32_t* r, uint32_t addr) {
    asm volatile("ldmatrix.sync.aligned.m8n8.x4.trans.shared.b16 {%0,%1,%2,%3}, [%4];"
                 : "=r"(r[0]), "=r"(r[1]), "=r"(r[2]), "=r"(r[3]) : "r"(addr));
}

__device__ __forceinline__ void mma16816(float* c, const uint32_t* a, const uint32_t* b) {
    asm volatile(
        "mma.sync.aligned.m16n8k16.row.col.f32.bf16.bf16.f32 "
        "{%0,%1,%2,%3}, {%4,%5,%6,%7}, {%8,%9}, {%0,%1,%2,%3};"
        : "+f"(c[0]), "+f"(c[1]), "+f"(c[2]), "+f"(c[3])
        : "r"(a[0]), "r"(a[1]), "r"(a[2]), "r"(a[3]), "r"(b[0]), "r"(b[1]));
}

// ---------------- W transpose (fp32, for recompute/decode) -------------------
__global__ void transpose_kernel(const float* __restrict__ W) {
    __shared__ float tile[32][33];
    int l0 = blockIdx.x * 32;
    int d0 = blockIdx.y * 32;
    int tx = threadIdx.x;      // 0..31
    int ty = threadIdx.y;      // 0..7
    #pragma unroll
    for (int r = ty; r < 32; r += 8)
        tile[r][tx] = W[(size_t)(d0 + r) * LL + (l0 + tx)];
    __syncthreads();
    #pragma unroll
    for (int r = ty; r < 32; r += 8)
        g_Wt[(size_t)(l0 + r) * DD + (d0 + tx)] = tile[tx][r];
}

// ---------------- fp32 -> bf16 converters ------------------------------------
__global__ __launch_bounds__(256) void convert_x_kernel(const float* __restrict__ X) {
    size_t i = (size_t)blockIdx.x * 256 + threadIdx.x;   // over BB*DD/4 float4s
    float4 v = ((const float4*)X)[i];
    __nv_bfloat16 o[4];
    o[0] = __float2bfloat16(v.x);
    o[1] = __float2bfloat16(v.y);
    o[2] = __float2bfloat16(v.z);
    o[3] = __float2bfloat16(v.w);
    *(uint2*)(&g_XB[i * 4]) = *(uint2*)o;
}

__global__ __launch_bounds__(256) void convert_w_kernel(const float* __restrict__ W) {
    size_t i = (size_t)blockIdx.x * 256 + threadIdx.x;   // over DD*LL/4 float4s
    float4 v = ((const float4*)W)[i];
    __nv_bfloat16 o[4];
    o[0] = __float2bfloat16(v.x);
    o[1] = __float2bfloat16(v.y);
    o[2] = __float2bfloat16(v.z);
    o[3] = __float2bfloat16(v.w);
    *(uint2*)(&g_WB[i * 4]) = *(uint2*)o;
}

// ---------------- encode GEMM via mma.sync bf16 ------------------------------
// Z[B,L] = X[B,D] @ W[D,L]; A row-major, B col-major-per-n (W is [k][n], ldmatrix.trans)
#define BM 128
#define BN 128
#define BK 32
#define STG 3
#define ASTRIDE 40                 // bf16 elems per A smem row (pad 32->40)
#define BSTRIDE 136                // bf16 elems per B smem row (pad 128->136)
#define ASTG_B (BM * ASTRIDE * 2)  // 10240 B
#define BSTG_B (BK * BSTRIDE * 2)  // 8704 B
#define GEMM_SMEM (STG * (ASTG_B + BSTG_B) + 512)

__global__ __launch_bounds__(256) void encode_gemm_mma(const float* __restrict__ benc) {
    extern __shared__ unsigned char dynsm[];
    const uint32_t sbase = (uint32_t)__cvta_generic_to_shared(dynsm);
    const uint32_t sA = sbase;
    const uint32_t sB = sbase + STG * ASTG_B;
    float* sbias = (float*)(dynsm + STG * (ASTG_B + BSTG_B));

    const int tid = threadIdx.x;
    const int lane = tid & 31;
    const int wid = tid >> 5;
    const int warp_m = wid >> 1;     // 0..3  -> 32 rows each
    const int warp_n = wid & 1;      // 0..1  -> 64 cols each
    const int row0 = blockIdx.x * BM;
    const int n0   = blockIdx.y * BN;

    if (tid < BN) sbias[tid] = benc[n0 + tid];

    // ldmatrix per-lane offsets
    const int a_r = lane & 15;                 // row within 16
    const int a_k = (lane >> 4) << 3;          // k offset 0/8
    const int b_k = (lane & 7) + ((lane >> 3) & 1) * 8;  // k row 0..15
    const int b_n = (lane >> 4) << 3;          // n offset 0/8

    // stage loader
    auto load_stage = [&](int s, int buf) {
        const int k0 = s * BK;
        #pragma unroll
        for (int c = tid; c < 512; c += 256) {       // A: 128 rows x 4 chunks
            int r = c >> 2, col = (c & 3) * 8;
            cp16(sA + buf * ASTG_B + r * (ASTRIDE * 2) + col * 2,
                 g_XB + (size_t)(row0 + r) * DD + k0 + col);
        }
        #pragma unroll
        for (int c = tid; c < 512; c += 256) {       // B: 32 rows x 16 chunks
            int r = c >> 4, col = (c & 15) * 8;
            cp16(sB + buf * BSTG_B + r * (BSTRIDE * 2) + col * 2,
                 g_WB + (size_t)(k0 + r) * LL + n0 + col);
        }
    };

    #pragma unroll
    for (int s = 0; s < STG; s++) {
        load_stage(s, s);
        asm volatile("cp.async.commit_group;" ::: "memory");
    }

    float acc[2][8][4];
    #pragma unroll
    for (int i = 0; i < 2; i++)
        #pragma unroll
        for (int j = 0; j < 8; j++)
            #pragma unroll
            for (int q = 0; q < 4; q++) acc[i][j][q] = 0.0f;

    const int NST = DD / BK;   // 64
    for (int s = 0; s < NST; s++) {
        asm volatile("cp.async.wait_group 2;" ::: "memory");
        __syncthreads();
        const int buf = s % STG;
        const uint32_t a_base = sA + buf * ASTG_B;
        const uint32_t b_base = sB + buf * BSTG_B;

        #pragma unroll
        for (int kk = 0; kk < BK; kk += 16) {
            uint32_t a[2][4], bq[4][4];
            #pragma unroll
            for (int i = 0; i < 2; i++)
                ldsm_x4(a[i], a_base + (warp_m * 32 + i * 16 + a_r) * (ASTRIDE * 2)
                              + (kk + a_k) * 2);
            #pragma unroll
            for (int j = 0; j < 4; j++)
                ldsm_x4_t(bq[j], b_base + (kk + b_k) * (BSTRIDE * 2)
                                + (warp_n * 64 + j * 16 + b_n) * 2);
            #pragma unroll
            for (int i = 0; i < 2; i++)
                #pragma unroll
                for (int j = 0; j < 8; j++)
                    mma16816(acc[i][j], a[i], &bq[j >> 1][(j & 1) * 2]);
        }
        __syncthreads();
        if (s + STG < NST) load_stage(s + STG, buf);
        asm volatile("cp.async.commit_group;" ::: "memory");
    }

    // epilogue: z = acc + bias; store |z| as half
    #pragma unroll
    for (int i = 0; i < 2; i++) {
        const int r_lo = row0 + warp_m * 32 + i * 16 + (lane >> 2);
        #pragma unroll
        for (int j = 0; j < 8; j++) {
            const int cl = warp_n * 64 + j * 8 + (lane & 3) * 2;
            float z0 = fabsf(acc[i][j][0] + sbias[cl]);
            float z1 = fabsf(acc[i][j][1] + sbias[cl + 1]);
            float z2 = fabsf(acc[i][j][2] + sbias[cl]);
            float z3 = fabsf(acc[i][j][3] + sbias[cl + 1]);
            *(__half2*)(g_Zh + (size_t)r_lo * LL + n0 + cl)       = __floats2half2_rn(z0, z1);
            *(__half2*)(g_Zh + (size_t)(r_lo + 8) * LL + n0 + cl) = __floats2half2_rn(z2, z3);
        }
    }
}

// ---------------- candidate selection (per-row 16-bit radix + margin) -------
__global__ __launch_bounds__(256) void select_cand_kernel() {
    __shared__ unsigned short keys[LL];   // 32 KB
    __shared__ int hist[256];
    __shared__ int s_h, s_rem, s_ctk, s_cnt;

    const int row = blockIdx.x;
    const int tid = threadIdx.x;
    const __half* zr = g_Zh + (size_t)row * LL;

    #pragma unroll
    for (int i = 0; i < 8; i++) {   // 2048 uint4 total
        int v4 = tid + i * 256;
        ((uint4*)keys)[v4] = ((const uint4*)zr)[v4];
    }
    if (tid == 0) s_cnt = 0;
    hist[tid] = 0;
    __syncthreads();

    // pass 1: high byte
    for (int i = 0; i < 64; i++) {
        unsigned k = keys[tid + i * 256];
        atomicAdd(&hist[k >> 8], 1);
    }
    __syncthreads();
    if (tid == 0) {
        int r = KK;
        for (int b = 255; b >= 0; b--) {
            int c = hist[b];
            if (c >= r) { s_h = b; s_rem = r; break; }
            r -= c;
        }
    }
    __syncthreads();
    const unsigned hb = (unsigned)s_h;
    hist[tid] = 0;
    __syncthreads();

    // pass 2: low byte among keys with matching high byte
    for (int i = 0; i < 64; i++) {
        unsigned k = keys[tid + i * 256];
        if ((k >> 8) == hb) atomicAdd(&hist[k & 255], 1);
    }
    __syncthreads();
    if (tid == 0) {
        int r = s_rem; int lo = 0;
        for (int b = 255; b >= 0; b--) {
            int c = hist[b];
            if (c >= r) { lo = b; break; }
            r -= c;
        }
        unsigned short t64 = (unsigned short)((hb << 8) | (unsigned)lo);
        float tf = __half2float(__ushort_as_half(t64));
        float thr = fmaxf(tf - 0.09f, 0.0f);     // margin >> bf16 GEMM noise
        s_ctk = (int)(unsigned)__half_as_ushort(__float2half_rd(thr));
    }
    __syncthreads();
    const unsigned ctk = (unsigned)s_ctk;

    for (int i = 0; i < 64; i++) {
        int idx = tid + i * 256;
        if ((unsigned)keys[idx] >= ctk) {
            int p = atomicAdd(&s_cnt, 1);
            if (p < CAND_MAX) g_cand[(size_t)row * CAND_MAX + p] = idx;
        }
    }
    __syncthreads();
    if (tid == 0) g_cand_cnt[row] = min(s_cnt, CAND_MAX);
}

// ---------------- exact fp32 recompute + top-64 + scatter --------------------
__global__ __launch_bounds__(256) void recompute_kernel(
    const float* __restrict__ X, const float* __restrict__ benc,
    float* __restrict__ Zs) {
    __shared__ float sx[DD];            // 8 KB
    __shared__ float sval[CAND_MAX];
    __shared__ int   scid[CAND_MAX];
    __shared__ int   s_pos;

    const int row = blockIdx.x;
    const int tid = threadIdx.x;
    const int lid = tid & 31, wid = tid >> 5;   // 8 warps

    for (int i = tid; i < DD / 4; i += 256)
        ((float4*)sx)[i] = ((const float4*)(X + (size_t)row * DD))[i];
    if (tid == 0) s_pos = 0;
    const int nc = g_cand_cnt[row];
    __syncthreads();

    for (int c = wid; c < nc; c += 8) {
        int idx = g_cand[(size_t)row * CAND_MAX + c];
        const float* wp = g_Wt + (size_t)idx * DD;
        float acc = 0.0f;
        #pragma unroll 8
        for (int i = 0; i < DD / 32; i++)
            acc = fmaf(wp[lid + i * 32], sx[lid + i * 32], acc);
        #pragma unroll
        for (int o = 16; o > 0; o >>= 1)
            acc += __shfl_down_sync(0xffffffffu, acc, o);
        if (lid == 0) { sval[c] = acc + benc[idx]; scid[c] = idx; }
    }
    __syncthreads();

    // exact rank among candidates (|v| desc, lowest index wins on ties)
    for (int c = tid; c < nc; c += 256) {
        float v = sval[c];
        float av = fabsf(v);
        int id = scid[c];
        int rank = 0;
        for (int j = 0; j < nc; j++) {
            float aj = fabsf(sval[j]);
            if (aj > av || (aj == av && scid[j] < id)) rank++;
        }
        if (rank < KK) {
            int p = atomicAdd(&s_pos, 1);
            g_topk_idx[row * KK + p] = id;
            g_topk_val[row * KK + p] = v;
            Zs[(size_t)row * LL + id] = v;
        }
    }
}

// ---------------- decode: recon[b,:] = sum_j val_j * Wt[idx_j,:] + b_dec ----
__global__ __launch_bounds__(256) void decode_kernel(
    const float* __restrict__ bdec, float* __restrict__ R) {
    __shared__ int   sidx[KK];
    __shared__ float sval[KK];
    const int row = blockIdx.x;
    const int tid = threadIdx.x;
    if (tid < KK) {
        sidx[tid] = g_topk_idx[row * KK + tid];
        sval[tid] = g_topk_val[row * KK + tid];
    }
    __syncthreads();

    const int d0 = tid * 8;
    float acc[8];
    {
        float4 b0 = *(const float4*)(bdec + d0);
        float4 b1 = *(const float4*)(bdec + d0 + 4);
        acc[0]=b0.x; acc[1]=b0.y; acc[2]=b0.z; acc[3]=b0.w;
        acc[4]=b1.x; acc[5]=b1.y; acc[6]=b1.z; acc[7]=b1.w;
    }
    #pragma unroll 4
    for (int j = 0; j < KK; j++) {
        const float v = sval[j];
        const float* wp = g_Wt + (size_t)sidx[j] * DD + d0;
        float4 w0 = *(const float4*)(wp);
        float4 w1 = *(const float4*)(wp + 4);
        acc[0] = fmaf(v, w0.x, acc[0]);
        acc[1] = fmaf(v, w0.y, acc[1]);
        acc[2] = fmaf(v, w0.z, acc[2]);
        acc[3] = fmaf(v, w0.w, acc[3]);
        acc[4] = fmaf(v, w1.x, acc[4]);
        acc[5] = fmaf(v, w1.y, acc[5]);
        acc[6] = fmaf(v, w1.z, acc[6]);
        acc[7] = fmaf(v, w1.w, acc[7]);
    }
    float4 o0, o1;
    o0.x=acc[0]; o0.y=acc[1]; o0.z=acc[2]; o0.w=acc[3];
    o1.x=acc[4]; o1.y=acc[5]; o1.z=acc[6]; o1.w=acc[7];
    *(float4*)(R + (size_t)row * DD + d0)     = o0;
    *(float4*)(R + (size_t)row * DD + d0 + 4) = o1;
}

// ---------------- launch ------------------------------------------------------
extern "C" void kernel_launch(void* const* d_in, const int* in_sizes, int n_in,
                              void* d_out, int out_size) {
    const float* X    = (const float*)d_in[0];  // [B, D]
    const float* W    = (const float*)d_in[1];  // [D, L]
    const float* benc = (const float*)d_in[2];  // [L]
    const float* bdec = (const float*)d_in[3];  // [D]

    float* recon = (float*)d_out;                       // [B, D]
    float* Zs    = (float*)d_out + (size_t)BB * DD;     // [B, L] z_sparse

    static int attr_set = 0;
    if (!attr_set) {
        cudaFuncSetAttribute(encode_gemm_mma,
                             cudaFuncAttributeMaxDynamicSharedMemorySize, GEMM_SMEM);
        attr_set = 1;
    }

    // 1) W -> Wt fp32 (for recompute/decode)
    {
        dim3 grid(LL / 32, DD / 32);
        dim3 block(32, 8);
        transpose_kernel<<<grid, block>>>(W);
    }
    // 2) converts to bf16
    convert_x_kernel<<<(BB * DD / 4) / 256, 256>>>(X);
    convert_w_kernel<<<((size_t)DD * LL / 4) / 256, 256>>>(W);
    // 3) approx encode GEMM on tensor cores -> |z_approx| half
    {
        dim3 grid(BB / BM, LL / BN);   // x = m tiles, y = n tiles
        encode_gemm_mma<<<grid, 256, GEMM_SMEM>>>(benc);
    }
    // 4) zero z_sparse region
    cudaMemsetAsync(Zs, 0, (size_t)BB * LL * sizeof(float));
    // 5) candidate selection with safety margin
    select_cand_kernel<<<BB, 256>>>();
    // 6) exact fp32 recompute of candidates + exact top-64 + scatter
    recompute_kernel<<<BB, 256>>>(X, benc, Zs);
    // 7) decode
    decode_kernel<<<BB, 256>>>(bdec, recon);
}